// round 16
// baseline (speedup 1.0000x reference)
#include <cuda_runtime.h>
#include <cstdint>
#include <math.h>

// Problem: B=4, T=4096, C=2048, E=64, K=8
#define NTOK   16384
#define CDIM   2048
#define NEXP   64
#define KTOP   8
#define BM     128
#define BK     32
#define NCHUNK (CDIM / BK)   // 64
#define NKTOT  (NTOK * KTOP)
#define NTHR   512

// smem: A [2][128][36] fp32 row-major (pitch 36 -> conflict-free mma frag loads);
//       B [2][32][72] fp32 [k][n] with n XOR (k&0x38) swizzle.
// A region reused as logits [128][65] (33280B <= 36864B).
#define APITCH 36
#define BPITCH 72
#define ABUF   (BM * APITCH)     // 4608 floats
#define BBUF   (BK * BPITCH)     // 2304 floats
#define SMEM_DYN ((2 * ABUF + 2 * BBUF) * 4)   // 55296 bytes

__device__ float g_counts[NEXP];
__device__ int   g_done = 0;

// exact 3-way tf32 split: x == h + m + l in fp32 (h,m,l are tf32-representable)
__device__ __forceinline__ void split3(float x, unsigned& h, unsigned& m, unsigned& l) {
    asm("cvt.rna.tf32.f32 %0, %1;" : "=r"(h) : "f"(x));
    float r1 = x - __uint_as_float(h);
    asm("cvt.rna.tf32.f32 %0, %1;" : "=r"(m) : "f"(r1));
    float r2 = r1 - __uint_as_float(m);
    asm("cvt.rna.tf32.f32 %0, %1;" : "=r"(l) : "f"(r2));
}

__device__ __forceinline__ void mma_tf32(float* d, const unsigned* a, const unsigned* b) {
    asm volatile(
        "mma.sync.aligned.m16n8k8.row.col.f32.tf32.tf32.f32 "
        "{%0,%1,%2,%3}, {%4,%5,%6,%7}, {%8,%9}, {%0,%1,%2,%3};"
        : "+f"(d[0]), "+f"(d[1]), "+f"(d[2]), "+f"(d[3])
        : "r"(a[0]), "r"(a[1]), "r"(a[2]), "r"(a[3]), "r"(b[0]), "r"(b[1]));
}

// larger value wins; ties -> smaller expert index (matches jax.lax.top_k)
__device__ __forceinline__ unsigned long long sortkey(float v, int e) {
    unsigned u = __float_as_uint(v);
    u = (u & 0x80000000u) ? ~u : (u | 0x80000000u);
    return ((unsigned long long)u << 32) | (unsigned)(63 - e);
}

// Fused: GEMM (x @ W^T, 6-term 3xTF32-exact, per-chunk drained accumulation)
// -> logits -> top-8 -> outputs+bincount -> maxvio.
// Grid: 128 blocks (1/SM), 512 threads = 16 warps; warp = 16 tok x 32 exp (4 m16n8 tiles).
__global__ __launch_bounds__(NTHR, 1) void k_gate(
    const float* __restrict__ X,    // [NTOK, CDIM]
    const int* __restrict__ mask,   // [NTOK] bool as int32
    const float* __restrict__ W,    // [NEXP, CDIM]
    const float* __restrict__ gb,   // [NEXP]
    const float* __restrict__ eb,   // [NEXP]
    float* __restrict__ out,        // [NKTOT idx | NKTOT probs | 1 maxvio]
    int pos)
{
    extern __shared__ float smem[];
    __shared__ float sGb[NEXP], sEb[NEXP], sCnt[NEXP];
    __shared__ int sLast;

    float* As = smem;                   // [2][BM][APITCH]
    float* Bs = smem + 2 * ABUF;        // [2][BK][BPITCH]

    const int tid  = threadIdx.x;
    const int lane = tid & 31;
    const int wid  = tid >> 5;
    const int gr   = lane >> 2;         // group id 0..7
    const int tg   = lane & 3;          // thread-in-group 0..3
    const int m0   = (wid & 7) * 16;    // warp's token rows
    const int nh   = wid >> 3;          // warp's expert half (0/1)
    const int tok0 = blockIdx.x * BM;

    if (tid < NEXP) { sGb[tid] = gb[tid]; sEb[tid] = eb[tid]; sCnt[tid] = 0.f; }

    // global load mapping: A 1024 float4/chunk (2/thr), B 512 (1/thr)
    int ar[2], ac[2];
    const float* Ag[2];
#pragma unroll
    for (int p = 0; p < 2; p++) {
        int idx = tid + p * NTHR;
        ar[p] = idx >> 3; ac[p] = (idx & 7) * 4;
        Ag[p] = X + (size_t)(tok0 + ar[p]) * CDIM + ac[p];
    }
    const int br = tid >> 3, bc = (tid & 7) * 4;    // br: expert, bc: k
    const float* Bg = W + (size_t)br * CDIM + bc;

    // master accumulators (fp32, RN-folded once per chunk)
    float acc[4][4];
#pragma unroll
    for (int j = 0; j < 4; j++)
#pragma unroll
        for (int i = 0; i < 4; i++) acc[j][i] = 0.f;

    // ---- prologue: chunk 0 -> buffer 0 ----
    {
        float4 a[2], b;
#pragma unroll
        for (int p = 0; p < 2; p++) a[p] = *(const float4*)Ag[p];
        b = *(const float4*)Bg;
#pragma unroll
        for (int p = 0; p < 2; p++)
            *(float4*)(As + ar[p] * APITCH + ac[p]) = a[p];
#pragma unroll
        for (int c = 0; c < 4; c++) {
            const int k = bc + c;
            Bs[k * BPITCH + (br ^ (k & 0x38))] = ((const float*)&b)[c];
        }
    }
    __syncthreads();

    for (int t = 0; t < NCHUNK; t++) {
        const int cur = t & 1;
        float4 an[2], bn;
        if (t + 1 < NCHUNK) {
            const int off = (t + 1) * BK;
#pragma unroll
            for (int p = 0; p < 2; p++) an[p] = *(const float4*)(Ag[p] + off);
            bn = *(const float4*)(Bg + off);
        }

        const float* Ab = As + cur * ABUF;
        const float* Bb = Bs + cur * BBUF;

        // per-chunk fragment accumulators (zeroed -> short in-tensor-core chains)
        float dch[4][4];
#pragma unroll
        for (int j = 0; j < 4; j++)
#pragma unroll
            for (int i = 0; i < 4; i++) dch[j][i] = 0.f;

#pragma unroll
        for (int ks = 0; ks < 4; ks++) {
            const int kb = ks * 8;
            // A fragment (16x8 rows m0.., cols kb..) + exact 3-way split
            unsigned ah[4], am[4], al[4];
            {
                const float* ap = Ab + (m0 + gr) * APITCH + kb + tg;
                split3(ap[0],              ah[0], am[0], al[0]);
                split3(ap[8 * APITCH],     ah[1], am[1], al[1]);
                split3(ap[4],              ah[2], am[2], al[2]);
                split3(ap[8 * APITCH + 4], ah[3], am[3], al[3]);
            }
#pragma unroll
            for (int j = 0; j < 4; j++) {
                const int n0 = nh * 32 + j * 8;
                const int np = (n0 + gr) ^ (kb & 0x38);
                float y0 = Bb[(kb + tg) * BPITCH + np];
                float y1 = Bb[(kb + tg + 4) * BPITCH + np];
                unsigned bh[2], bm[2], bl[2];
                split3(y0, bh[0], bm[0], bl[0]);
                split3(y1, bh[1], bm[1], bl[1]);
                // small terms first, dominant hh last (minimizes large-|acc| roundings)
                mma_tf32(dch[j], am, bm);   // mm
                mma_tf32(dch[j], al, bh);   // lh
                mma_tf32(dch[j], ah, bl);   // hl
                mma_tf32(dch[j], am, bh);   // mh
                mma_tf32(dch[j], ah, bm);   // hm
                mma_tf32(dch[j], ah, bh);   // hh
            }
        }

        // drain: one RN add per value per chunk
#pragma unroll
        for (int j = 0; j < 4; j++)
#pragma unroll
            for (int i = 0; i < 4; i++) acc[j][i] += dch[j][i];

        if (t + 1 < NCHUNK) {
            float* Asn = As + (1 - cur) * ABUF;
            float* Bsn = Bs + (1 - cur) * BBUF;
#pragma unroll
            for (int p = 0; p < 2; p++)
                *(float4*)(Asn + ar[p] * APITCH + ac[p]) = an[p];
#pragma unroll
            for (int c = 0; c < 4; c++) {
                const int k = bc + c;
                Bsn[k * BPITCH + (br ^ (k & 0x38))] = ((const float*)&bn)[c];
            }
            __syncthreads();
        }
    }
    __syncthreads();   // GEMM done; smem free for reuse

    // ---- logits tile Ls[m][n], stride 65, +gate_bias ----
    float* Ls = smem;
#pragma unroll
    for (int j = 0; j < 4; j++) {
        const int n0 = nh * 32 + j * 8;
        const int col = n0 + 2 * tg;
        const int row = m0 + gr;
        Ls[row * 65 + col]           = acc[j][0] + sGb[col];
        Ls[row * 65 + col + 1]       = acc[j][1] + sGb[col + 1];
        Ls[(row + 8) * 65 + col]     = acc[j][2] + sGb[col];
        Ls[(row + 8) * 65 + col + 1] = acc[j][3] + sGb[col + 1];
    }
    __syncthreads();

    // ---- warp-per-token top-8 of 64 (proven epilogue); 16 warps x 8 tokens ----
    const float eb0 = sEb[lane], eb1 = sEb[lane + 32];
    for (int q = 0; q < 8; q++) {
        const int m = wid * 8 + q;
        const int tok = tok0 + m;
        const float* row = Ls + m * 65;
        const float g0 = row[lane], g1 = row[lane + 32];
        const float s0 = g0 + eb0, s1 = g1 + eb1;
        bool u0 = false, u1 = false;
        float selIdx = 0.f, selProb = 0.f;
        const int mk = mask[tok];

#pragma unroll
        for (int it = 0; it < KTOP; it++) {
            unsigned long long k0 = u0 ? 0ull : sortkey(s0, lane);
            unsigned long long k1 = u1 ? 0ull : sortkey(s1, lane + 32);
            unsigned long long key = k0 > k1 ? k0 : k1;
#pragma unroll
            for (int o = 16; o; o >>= 1) {
                unsigned long long oth = __shfl_xor_sync(0xffffffffu, key, o);
                if (oth > key) key = oth;
            }
            const int e = 63 - (int)(key & 63u);
            if (e == lane)      u0 = true;
            if (e == lane + 32) u1 = true;
            if (lane == it) {
                const float g = row[e];
                selIdx = (float)e;
                selProb = 1.f / (1.f + expf(-g));
                if (mk) atomicAdd(&sCnt[e], 1.f);
            }
        }
        float p = (lane < KTOP) ? selProb : 0.f;
        float sum = p;
#pragma unroll
        for (int o = 16; o; o >>= 1) sum += __shfl_xor_sync(0xffffffffu, sum, o);
        if (lane < KTOP) {
            out[(size_t)tok * KTOP + lane]         = selIdx;
            out[NKTOT + (size_t)tok * KTOP + lane] = selProb / sum;
        }
    }

    __syncthreads();
    if (tid < NEXP) {
        const float c = sCnt[tid];
        if (c != 0.f) atomicAdd(&g_counts[tid], c);
    }

    // ---- last block computes maxvio and resets scratch (deterministic) ----
    if (tid == 0) {
        __threadfence();
        sLast = (atomicAdd(&g_done, 1) == (int)gridDim.x - 1) ? 1 : 0;
    }
    __syncthreads();
    if (sLast && wid == 0) {
        float c0 = g_counts[lane], c1 = g_counts[lane + 32];
        float mx = fmaxf(c0, c1);
        float sm = c0 + c1;
#pragma unroll
        for (int o = 16; o; o >>= 1) {
            mx = fmaxf(mx, __shfl_xor_sync(0xffffffffu, mx, o));
            sm += __shfl_xor_sync(0xffffffffu, sm, o);
        }
        if (lane == 0) {
            const float avg = sm / 64.f;
            out[pos] = (mx - avg) / (avg + 1e-5f);
            g_done = 0;
        }
        g_counts[lane] = 0.f;
        g_counts[lane + 32] = 0.f;
    }
}

extern "C" void kernel_launch(void* const* d_in, const int* in_sizes, int n_in,
                              void* d_out, int out_size) {
    const float* X    = (const float*)d_in[0];
    const int*   mask = (const int*)d_in[1];
    const float* W    = (const float*)d_in[2];
    const float* gb   = (const float*)d_in[3];
    const float* eb   = (const float*)d_in[4];
    float*       out  = (float*)d_out;

    cudaFuncSetAttribute(k_gate, cudaFuncAttributeMaxDynamicSharedMemorySize, SMEM_DYN);
    k_gate<<<NTOK / BM, NTHR, SMEM_DYN>>>(X, mask, W, gb, eb, out, out_size - 1);
}

// round 17
// speedup vs baseline: 2.0108x; 2.0108x over previous
#include <cuda_runtime.h>
#include <cstdint>
#include <math.h>

// Problem: B=4, T=4096, C=2048, E=64, K=8
#define NTOK   16384
#define CDIM   2048
#define NEXP   64
#define KTOP   8
#define BM     128
#define BK     32
#define NCHUNK (CDIM / BK)   // 64
#define NKTOT  (NTOK * KTOP)
#define NTHR   512

// smem (u32 units): pre-split bf16 tiles, double buffered.
// A: [2][3 terms][128 rows][36 u32]  (row = token, 32 u32 = 64 bf16 k-values + 4 pad)
// B: [2][3 terms][64 rows][36 u32]   (row = expert)
// pitch 36 u32 = 144B -> frag loads bank = 4*gr+tg, conflict-free.
#define ATERM  (128 * 36)          // 4608 u32
#define ABUFU  (3 * ATERM)         // per buffer
#define BTERM  (64 * 36)           // 2304 u32
#define BBUFU  (3 * BTERM)
#define SMEM_U32 (2 * ABUFU + 2 * BBUFU)   // 41472 u32
#define SMEM_DYN (SMEM_U32 * 4)            // 165888 bytes

__device__ float g_counts[NEXP];
__device__ int   g_done = 0;

// pack two floats -> bf16x2 (RN; random-sign residuals, no RZ bias)
__device__ __forceinline__ unsigned pack2rn(float lo, float hi) {
    unsigned r;
    asm("cvt.rn.bf16x2.f32 %0, %1, %2;" : "=r"(r) : "f"(hi), "f"(lo));
    return r;
}
// 3-way RN bf16 split of a value pair: x = h + m + l + O(2^-24 x)
__device__ __forceinline__ void split_pair(float x0, float x1,
                                           unsigned& h, unsigned& m, unsigned& l) {
    h = pack2rn(x0, x1);
    float r0 = x0 - __uint_as_float(h << 16);
    float r1 = x1 - __uint_as_float(h & 0xFFFF0000u);
    m = pack2rn(r0, r1);
    r0 -= __uint_as_float(m << 16);
    r1 -= __uint_as_float(m & 0xFFFF0000u);
    l = pack2rn(r0, r1);
}

__device__ __forceinline__ void mma_bf16(float* d, const unsigned* a, const unsigned* b) {
    asm volatile(
        "mma.sync.aligned.m16n8k16.row.col.f32.bf16.bf16.f32 "
        "{%0,%1,%2,%3}, {%4,%5,%6,%7}, {%8,%9}, {%0,%1,%2,%3};"
        : "+f"(d[0]), "+f"(d[1]), "+f"(d[2]), "+f"(d[3])
        : "r"(a[0]), "r"(a[1]), "r"(a[2]), "r"(a[3]), "r"(b[0]), "r"(b[1]));
}

// larger value wins; ties -> smaller expert index (matches jax.lax.top_k)
__device__ __forceinline__ unsigned long long sortkey(float v, int e) {
    unsigned u = __float_as_uint(v);
    u = (u & 0x80000000u) ? ~u : (u | 0x80000000u);
    return ((unsigned long long)u << 32) | (unsigned)(63 - e);
}

// store one float4 (4 consecutive k) as 3 split bf16 tiles
__device__ __forceinline__ void store_split4(unsigned* Th, unsigned* Tm, unsigned* Tl,
                                             int row, int col4, float4 v) {
    unsigned h0, m0, l0, h1, m1, l1;
    split_pair(v.x, v.y, h0, m0, l0);
    split_pair(v.z, v.w, h1, m1, l1);
    const int o = row * 36 + (col4 >> 1);   // col4 multiple of 4 -> u32 idx even
    *(uint2*)(Th + o) = make_uint2(h0, h1);
    *(uint2*)(Tm + o) = make_uint2(m0, m1);
    *(uint2*)(Tl + o) = make_uint2(l0, l1);
}

// Fused: GEMM (x @ W^T, 6-term bf16-split, pre-split smem tiles, per-chunk drain)
// -> logits -> top-8 -> outputs+bincount -> maxvio.
// Grid: 128 blocks (1/SM), 512 threads = 16 warps; warp = 16 tok x 32 exp (4 m16n8 tiles).
__global__ __launch_bounds__(NTHR, 1) void k_gate(
    const float* __restrict__ X,    // [NTOK, CDIM]
    const int* __restrict__ mask,   // [NTOK] bool as int32
    const float* __restrict__ W,    // [NEXP, CDIM]
    const float* __restrict__ gb,   // [NEXP]
    const float* __restrict__ eb,   // [NEXP]
    float* __restrict__ out,        // [NKTOT idx | NKTOT probs | 1 maxvio]
    int pos)
{
    extern __shared__ unsigned usmem[];
    __shared__ float sGb[NEXP], sEb[NEXP], sCnt[NEXP];
    __shared__ int sLast;

    unsigned* SA = usmem;               // A tiles
    unsigned* SB = usmem + 2 * ABUFU;   // B tiles

    const int tid  = threadIdx.x;
    const int lane = tid & 31;
    const int wid  = tid >> 5;
    const int gr   = lane >> 2;         // group 0..7
    const int tg   = lane & 3;          // 0..3
    const int m0   = (wid & 7) * 16;    // warp token rows
    const int nh   = wid >> 3;          // expert half
    const int tok0 = blockIdx.x * BM;

    if (tid < NEXP) { sGb[tid] = gb[tid]; sEb[tid] = eb[tid]; sCnt[tid] = 0.f; }

    // global load mapping: A 1024 float4/chunk (2/thr), B 512 (1/thr)
    int ar[2], ac[2];
    const float* Ag[2];
#pragma unroll
    for (int p = 0; p < 2; p++) {
        int idx = tid + p * NTHR;
        ar[p] = idx >> 3; ac[p] = (idx & 7) * 4;
        Ag[p] = X + (size_t)(tok0 + ar[p]) * CDIM + ac[p];
    }
    const int br = tid >> 3, bc = (tid & 7) * 4;
    const float* Bg = W + (size_t)br * CDIM + bc;

    // master accumulators (fp32, RN-folded once per chunk)
    float acc[4][4];
#pragma unroll
    for (int j = 0; j < 4; j++)
#pragma unroll
        for (int i = 0; i < 4; i++) acc[j][i] = 0.f;

    // ---- prologue: chunk 0 -> buffer 0 (split at store) ----
    {
        float4 a[2], b;
#pragma unroll
        for (int p = 0; p < 2; p++) a[p] = *(const float4*)Ag[p];
        b = *(const float4*)Bg;
#pragma unroll
        for (int p = 0; p < 2; p++)
            store_split4(SA, SA + ATERM, SA + 2 * ATERM, ar[p], ac[p], a[p]);
        store_split4(SB, SB + BTERM, SB + 2 * BTERM, br, bc, b);
    }
    __syncthreads();

    for (int t = 0; t < NCHUNK; t++) {
        const int cur = t & 1;
        float4 an[2], bn;
        if (t + 1 < NCHUNK) {
            const int off = (t + 1) * BK;
#pragma unroll
            for (int p = 0; p < 2; p++) an[p] = *(const float4*)(Ag[p] + off);
            bn = *(const float4*)(Bg + off);
        }

        const unsigned* Ah = SA + cur * ABUFU;
        const unsigned* Bh = SB + cur * BBUFU;

        // per-chunk fragment accumulators (short tensor-core chains)
        float dch[4][4];
#pragma unroll
        for (int j = 0; j < 4; j++)
#pragma unroll
            for (int i = 0; i < 4; i++) dch[j][i] = 0.f;

#pragma unroll
        for (int kg = 0; kg < 2; kg++) {            // two K=16 groups per chunk
            unsigned ah[4], am[4], al[4];
            {
                const unsigned* ap = Ah + (m0 + gr) * 36 + kg * 8 + tg;
                ah[0] = ap[0];          ah[1] = ap[8 * 36];
                ah[2] = ap[4];          ah[3] = ap[8 * 36 + 4];
                am[0] = ap[ATERM];      am[1] = ap[ATERM + 8 * 36];
                am[2] = ap[ATERM + 4];  am[3] = ap[ATERM + 8 * 36 + 4];
                al[0] = ap[2 * ATERM];  al[1] = ap[2 * ATERM + 8 * 36];
                al[2] = ap[2 * ATERM + 4]; al[3] = ap[2 * ATERM + 8 * 36 + 4];
            }
#pragma unroll
            for (int j = 0; j < 4; j++) {
                const int n0 = nh * 32 + j * 8;
                const unsigned* bp = Bh + (n0 + gr) * 36 + kg * 8 + tg;
                unsigned bh[2], bm[2], bl[2];
                bh[0] = bp[0];             bh[1] = bp[4];
                bm[0] = bp[BTERM];         bm[1] = bp[BTERM + 4];
                bl[0] = bp[2 * BTERM];     bl[1] = bp[2 * BTERM + 4];
                // small terms first, dominant hh last
                mma_bf16(dch[j], am, bm);   // mm
                mma_bf16(dch[j], al, bh);   // lh
                mma_bf16(dch[j], ah, bl);   // hl
                mma_bf16(dch[j], am, bh);   // mh
                mma_bf16(dch[j], ah, bm);   // hm
                mma_bf16(dch[j], ah, bh);   // hh
            }
        }

        // drain: one RN add per value per chunk
#pragma unroll
        for (int j = 0; j < 4; j++)
#pragma unroll
            for (int i = 0; i < 4; i++) acc[j][i] += dch[j][i];

        if (t + 1 < NCHUNK) {
            unsigned* SAn = SA + (1 - cur) * ABUFU;
            unsigned* SBn = SB + (1 - cur) * BBUFU;
#pragma unroll
            for (int p = 0; p < 2; p++)
                store_split4(SAn, SAn + ATERM, SAn + 2 * ATERM, ar[p], ac[p], an[p]);
            store_split4(SBn, SBn + BTERM, SBn + 2 * BTERM, br, bc, bn);
            __syncthreads();
        }
    }
    __syncthreads();   // GEMM done; smem free for reuse

    // ---- logits tile Ls[m][n], stride 65, +gate_bias ----
    float* Ls = (float*)usmem;
#pragma unroll
    for (int j = 0; j < 4; j++) {
        const int n0 = nh * 32 + j * 8;
        const int col = n0 + 2 * tg;
        const int row = m0 + gr;
        Ls[row * 65 + col]           = acc[j][0] + sGb[col];
        Ls[row * 65 + col + 1]       = acc[j][1] + sGb[col + 1];
        Ls[(row + 8) * 65 + col]     = acc[j][2] + sGb[col];
        Ls[(row + 8) * 65 + col + 1] = acc[j][3] + sGb[col + 1];
    }
    __syncthreads();

    // ---- warp-per-token top-8 of 64 (proven epilogue); 16 warps x 8 tokens ----
    const float eb0 = sEb[lane], eb1 = sEb[lane + 32];
    for (int q = 0; q < 8; q++) {
        const int m = wid * 8 + q;
        const int tok = tok0 + m;
        const float* row = Ls + m * 65;
        const float g0 = row[lane], g1 = row[lane + 32];
        const float s0 = g0 + eb0, s1 = g1 + eb1;
        bool u0 = false, u1 = false;
        float selIdx = 0.f, selProb = 0.f;
        const int mk = mask[tok];

#pragma unroll
        for (int it = 0; it < KTOP; it++) {
            unsigned long long k0 = u0 ? 0ull : sortkey(s0, lane);
            unsigned long long k1 = u1 ? 0ull : sortkey(s1, lane + 32);
            unsigned long long key = k0 > k1 ? k0 : k1;
#pragma unroll
            for (int o = 16; o; o >>= 1) {
                unsigned long long oth = __shfl_xor_sync(0xffffffffu, key, o);
                if (oth > key) key = oth;
            }
            const int e = 63 - (int)(key & 63u);
            if (e == lane)      u0 = true;
            if (e == lane + 32) u1 = true;
            if (lane == it) {
                const float g = row[e];
                selIdx = (float)e;
                selProb = 1.f / (1.f + expf(-g));
                if (mk) atomicAdd(&sCnt[e], 1.f);
            }
        }
        float p = (lane < KTOP) ? selProb : 0.f;
        float sum = p;
#pragma unroll
        for (int o = 16; o; o >>= 1) sum += __shfl_xor_sync(0xffffffffu, sum, o);
        if (lane < KTOP) {
            out[(size_t)tok * KTOP + lane]         = selIdx;
            out[NKTOT + (size_t)tok * KTOP + lane] = selProb / sum;
        }
    }

    __syncthreads();
    if (tid < NEXP) {
        const float c = sCnt[tid];
        if (c != 0.f) atomicAdd(&g_counts[tid], c);
    }

    // ---- last block computes maxvio and resets scratch (deterministic) ----
    if (tid == 0) {
        __threadfence();
        sLast = (atomicAdd(&g_done, 1) == (int)gridDim.x - 1) ? 1 : 0;
    }
    __syncthreads();
    if (sLast && wid == 0) {
        float c0 = g_counts[lane], c1 = g_counts[lane + 32];
        float mx = fmaxf(c0, c1);
        float sm = c0 + c1;
#pragma unroll
        for (int o = 16; o; o >>= 1) {
            mx = fmaxf(mx, __shfl_xor_sync(0xffffffffu, mx, o));
            sm += __shfl_xor_sync(0xffffffffu, sm, o);
        }
        if (lane == 0) {
            const float avg = sm / 64.f;
            out[pos] = (mx - avg) / (avg + 1e-5f);
            g_done = 0;
        }
        g_counts[lane] = 0.f;
        g_counts[lane + 32] = 0.f;
    }
}

extern "C" void kernel_launch(void* const* d_in, const int* in_sizes, int n_in,
                              void* d_out, int out_size) {
    const float* X    = (const float*)d_in[0];
    const int*   mask = (const int*)d_in[1];
    const float* W    = (const float*)d_in[2];
    const float* gb   = (const float*)d_in[3];
    const float* eb   = (const float*)d_in[4];
    float*       out  = (float*)d_out;

    cudaFuncSetAttribute(k_gate, cudaFuncAttributeMaxDynamicSharedMemorySize, SMEM_DYN);
    k_gate<<<NTOK / BM, NTHR, SMEM_DYN>>>(X, mask, W, gb, eb, out, out_size - 1);
}